// round 17
// baseline (speedup 1.0000x reference)
#include <cuda_runtime.h>
#include <cuda_fp16.h>
#include <cstdint>

#define DI __device__ __forceinline__

constexpr int NB = 16, SEQ = 4096, INF = 1024, OUTF = 1024, RR = 16, NSK = 16;
constexpr int MTOT = NB * SEQ;                    // 65536
constexpr int MG0 = 4096;                         // batch 0 (256 CTAs = 1 wave)
constexpr int MG1 = MTOT - MG0;                   // batches 1-15

// ---------------- device scratch (allocation-free) ----------------
__device__ __half d_Weff[(size_t)NB * OUTF * INF];// 32 MB, [b][n][k] K-major
__device__ float  d_wA[NB * INF * RR];
__device__ float  d_wB[NB * RR * OUTF];

// ---------------- prep kernels ----------------
__global__ void k_wAB(const float* __restrict__ A, const float* __restrict__ Bm,
                      const float* __restrict__ sl, const int* __restrict__ tid_) {
    int gid = blockIdx.x * 256 + threadIdx.x;     // < 524288
    int hi = gid >> 18, e = gid & 262143;
    int b = e >> 14, j = e & 16383;
    __shared__ float lg[NSK];
    __shared__ float ssum;
    if (threadIdx.x < NSK) {
        float v = 1.f / (1.f + expf(-sl[tid_[b] * NSK + threadIdx.x]));
        lg[threadIdx.x] = v;
    }
    __syncthreads();
    if (threadIdx.x == 0) {
        float s = 0.f;
#pragma unroll
        for (int k = 0; k < NSK; ++k) s += lg[k];
        ssum = 1.f / (s + 1e-12f);
    }
    __syncthreads();
    const float* src = hi ? Bm : A;
    float acc = 0.f;
#pragma unroll
    for (int s = 0; s < NSK; ++s) acc += lg[s] * src[s * 16384 + j];
    acc *= ssum;
    if (hi) d_wB[e] = acc; else d_wA[e] = acc;
}

// block (with blk_off) = (b, ot in [0,32)): 32 o's per block, 4 i per thread.
__global__ void __launch_bounds__(256) k_weff(const float* __restrict__ weight, int blk_off) {
    int blk = blockIdx.x + blk_off;
    int b = blk >> 5, ot = blk & 31;
    __shared__ float wBs[32 * RR];                 // [o_local][r]
    for (int t = threadIdx.x; t < 32 * RR; t += 256) {
        int ol = t >> 4, r = t & 15;
        wBs[t] = d_wB[b * 16384 + r * OUTF + ot * 32 + ol];
    }
    __syncthreads();
    const int i0 = threadIdx.x * 4;
    float wa[4][RR];
#pragma unroll
    for (int ii = 0; ii < 4; ++ii) {
#pragma unroll
        for (int r = 0; r < RR; r += 4) {
            float4 v = *(const float4*)(d_wA + b * 16384 + (i0 + ii) * RR + r);
            wa[ii][r] = v.x; wa[ii][r + 1] = v.y; wa[ii][r + 2] = v.z; wa[ii][r + 3] = v.w;
        }
    }
#pragma unroll 4
    for (int ol = 0; ol < 32; ++ol) {
        int o = ot * 32 + ol;
        float4 w = *(const float4*)(weight + (size_t)o * INF + i0);
        float acc[4] = {0.f, 0.f, 0.f, 0.f};
#pragma unroll
        for (int r = 0; r < RR; ++r) {
            float wb = wBs[ol * RR + r];
            acc[0] += wa[0][r] * wb; acc[1] += wa[1][r] * wb;
            acc[2] += wa[2][r] * wb; acc[3] += wa[3][r] * wb;
        }
        __half2 h0 = __floats2half2_rn(w.x + acc[0] * (1.f / RR), w.y + acc[1] * (1.f / RR));
        __half2 h1 = __floats2half2_rn(w.z + acc[2] * (1.f / RR), w.w + acc[3] * (1.f / RR));
        uint2 u;
        u.x = *reinterpret_cast<uint32_t*>(&h0);
        u.y = *reinterpret_cast<uint32_t*>(&h1);
        *reinterpret_cast<uint2*>(d_Weff + (size_t)b * (OUTF * INF) + (size_t)o * INF + i0) = u;
    }
}

// ---------------- GEMM config ----------------
constexpr int BM = 128, BN = 128, BK = 64;        // K chunk = 64 halfs = 128 B rows
constexpr int NCHUNK = INF / BK;                  // 16
constexpr int STAGE_BYTES = 32768;                // A16 16K + B 16K
constexpr int SM_B = 16384;
constexpr int SMEM_TOTAL = 1024 + 3 * STAGE_BYTES;   // 99328 (2 CTAs/SM)

DI uint32_t s2u(const void* p) {
    uint32_t a;
    asm("{ .reg .u64 t; cvta.to.shared.u64 t, %1; cvt.u32.u64 %0, t; }" : "=r"(a) : "l"(p));
    return a;
}
DI void cp16(uint32_t dst, const void* src) {
    asm volatile("cp.async.cg.shared.global [%0], [%1], 16;" :: "r"(dst), "l"(src));
}
DI void cp_commit() { asm volatile("cp.async.commit_group;" ::: "memory"); }
template <int N> DI void cp_wait() { asm volatile("cp.async.wait_group %0;" :: "n"(N) : "memory"); }

DI void ldsm4(uint32_t addr, uint32_t* r) {
    asm volatile("ldmatrix.sync.aligned.m8n8.x4.shared.b16 {%0,%1,%2,%3}, [%4];"
                 : "=r"(r[0]), "=r"(r[1]), "=r"(r[2]), "=r"(r[3]) : "r"(addr));
}
DI void mma16816(float* c, const uint32_t* a, const uint32_t* b) {
    asm volatile(
        "mma.sync.aligned.m16n8k16.row.col.f32.f16.f16.f32 "
        "{%0,%1,%2,%3}, {%4,%5,%6,%7}, {%8,%9}, {%0,%1,%2,%3};"
        : "+f"(c[0]), "+f"(c[1]), "+f"(c[2]), "+f"(c[3])
        : "r"(a[0]), "r"(a[1]), "r"(a[2]), "r"(a[3]), "r"(b[0]), "r"(b[1]));
}

// B fill: 128 rows x 128 B via cp.async (fp16 Weff, swizzled)
DI void fillB(uint32_t stg, const __half* Bptr, int tid) {
#pragma unroll
    for (int j = 0; j < 8; ++j) {
        int idx = tid + j * 128;
        int row = idx >> 3, seg = idx & 7;
        uint32_t off = row * 128 + ((seg * 16) ^ ((row & 7) << 4));
        cp16(stg + SM_B + off, Bptr + row * 1024 + seg * 8);
    }
    cp_commit();
}

// A quarter-chunk: rows [q*32, q*32+32), thread t: row q*32+(t>>2), cols (t&3)*16
DI void ldgA(float4* buf, const float* Achunk, int q, int tid) {
    const float4* p = (const float4*)(Achunk + (size_t)(q * 32 + (tid >> 2)) * INF
                                      + (tid & 3) * 16);
#pragma unroll
    for (int j = 0; j < 4; ++j) buf[j] = __ldg(p + j);
}
DI void stsA(uint32_t stg, const float4* buf, int q, int tid) {
    int R = q * 32 + (tid >> 2);
    uint32_t base = stg + R * 128;
    int seg0 = (tid & 3) * 2;
#pragma unroll
    for (int s = 0; s < 2; ++s) {
        __half2 a = __floats2half2_rn(buf[2 * s].x, buf[2 * s].y);
        __half2 b = __floats2half2_rn(buf[2 * s].z, buf[2 * s].w);
        __half2 c = __floats2half2_rn(buf[2 * s + 1].x, buf[2 * s + 1].y);
        __half2 d = __floats2half2_rn(buf[2 * s + 1].z, buf[2 * s + 1].w);
        uint32_t off = (uint32_t)(((seg0 + s) * 16) ^ ((R & 7) << 4));
        asm volatile("st.shared.v4.b32 [%0], {%1, %2, %3, %4};"
                     :: "r"(base + off),
                        "r"(*reinterpret_cast<uint32_t*>(&a)),
                        "r"(*reinterpret_cast<uint32_t*>(&b)),
                        "r"(*reinterpret_cast<uint32_t*>(&c)),
                        "r"(*reinterpret_cast<uint32_t*>(&d)) : "memory");
    }
}

// ---------------- GEMM kernel (fused fp32->fp16 A convert) ----------------
__global__ void __launch_bounds__(128, 2)
k_gemm(const float* __restrict__ bias, float* __restrict__ out, int m_base,
       const float* __restrict__ input) {
    extern __shared__ char smem_raw[];
    uint32_t sb = (s2u(smem_raw) + 1023u) & ~1023u;
    const int tid = threadIdx.x, lane = tid & 31, w = tid >> 5;
    const int wm = w >> 1, wn = w & 1;            // warp tile 64x64 in 2x2 grid
    const int m0 = m_base + blockIdx.y * BM;
    const int n0 = blockIdx.x * BN;
    const int b  = m0 >> 12;

    const float*  Ain   = input + (size_t)m0 * INF;
    const __half* Bbase = d_Weff + (size_t)b * (OUTF * INF) + (size_t)n0 * INF;

    // prologue: B stages 0,1 via cp.async; A stages 0,1 via LDG+cvt+STS
    fillB(sb, Bbase, tid);
    fillB(sb + STAGE_BYTES, Bbase + BK, tid);
    float4 buf[4];
#pragma unroll
    for (int q = 0; q < 4; ++q) { ldgA(buf, Ain, q, tid); stsA(sb, buf, q, tid); }
#pragma unroll
    for (int q = 0; q < 4; ++q) {
        ldgA(buf, Ain + BK, q, tid); stsA(sb + STAGE_BYTES, buf, q, tid);
    }
    ldgA(buf, Ain + 2 * BK, 0, tid);              // A2 q0 in flight

    float c[4][8][4];
#pragma unroll
    for (int i = 0; i < 4; ++i)
#pragma unroll
        for (int j = 0; j < 8; ++j)
#pragma unroll
            for (int q = 0; q < 4; ++q) c[i][j][q] = 0.f;

    const int a_row = wm * 64 + (lane & 15);                      // + mt*16
    const int a_kb  = (lane >> 4) * 16;
    const int b_row = wn * 64 + ((lane >> 4) << 3) + (lane & 7);  // + p*16
    const int b_kb  = ((lane >> 3) & 1) * 16;

    int st = 0, fs = 2;
#pragma unroll 1
    for (int i = 0; i < NCHUNK; ++i) {
        if (i < NCHUNK - 1) cp_wait<1>();
        else cp_wait<0>();
        __syncthreads();

        uint32_t as = sb + st * STAGE_BYTES;
        uint32_t bs = as + SM_B;
        uint32_t nstg = sb + fs * STAGE_BYTES;
        bool do_fill = (i + 2 < NCHUNK);
        const float* Anext = Ain + (i + 2) * BK;

        if (do_fill) {
            stsA(nstg, buf, 0, tid);              // A_{i+2} q0
            ldgA(buf, Anext, 1, tid);
            fillB(nstg, Bbase + (i + 2) * BK, tid);
        }

#pragma unroll
        for (int kk = 0; kk < 4; ++kk) {
            uint32_t af[4][4], bf[8][2];
#pragma unroll
            for (int mt = 0; mt < 4; ++mt) {
                int row = a_row + mt * 16;
                ldsm4(as + row * 128 + ((kk * 32 + a_kb) ^ ((row & 7) << 4)), af[mt]);
            }
#pragma unroll
            for (int p = 0; p < 4; ++p) {
                int row = b_row + p * 16;
                uint32_t r[4];
                ldsm4(bs + row * 128 + ((kk * 32 + b_kb) ^ ((row & 7) << 4)), r);
                bf[p * 2][0] = r[0]; bf[p * 2][1] = r[1];
                bf[p * 2 + 1][0] = r[2]; bf[p * 2 + 1][1] = r[3];
            }
#pragma unroll
            for (int mt = 0; mt < 4; ++mt)
#pragma unroll
                for (int nt = 0; nt < 8; ++nt)
                    mma16816(c[mt][nt], af[mt], bf[nt]);

            // A pipeline rounds between kk blocks
            if (do_fill && kk < 3) {
                stsA(nstg, buf, kk + 1, tid);     // A_{i+2} q(kk+1)
                if (kk < 2) ldgA(buf, Anext, kk + 2, tid);
                else if (i + 3 < NCHUNK) ldgA(buf, Ain + (i + 3) * BK, 0, tid);
            }
        }
        st = (st == 2) ? 0 : st + 1;
        fs = (fs == 2) ? 0 : fs + 1;
    }

    // ---- epilogue ----
#pragma unroll
    for (int mt = 0; mt < 4; ++mt) {
        int r0 = m0 + wm * 64 + mt * 16 + (lane >> 2);
#pragma unroll
        for (int nt = 0; nt < 8; ++nt) {
            int cn = n0 + wn * 64 + nt * 8 + (lane & 3) * 2;
            float bx = __ldg(bias + cn), by = __ldg(bias + cn + 1);
            float2 v0 = make_float2(c[mt][nt][0] + bx, c[mt][nt][1] + by);
            float2 v1 = make_float2(c[mt][nt][2] + bx, c[mt][nt][3] + by);
            *reinterpret_cast<float2*>(out + (size_t)r0 * OUTF + cn) = v0;
            *reinterpret_cast<float2*>(out + (size_t)(r0 + 8) * OUTF + cn) = v1;
        }
    }
}

// ---------------- launch: convert deleted; s2 = weff_rest only ----------------
extern "C" void kernel_launch(void* const* d_in, const int* in_sizes, int n_in,
                              void* d_out, int out_size) {
    const float* input  = (const float*)d_in[0];
    const float* slog   = (const float*)d_in[1];
    const float* weight = (const float*)d_in[2];
    const float* bias   = (const float*)d_in[3];
    const float* swA    = (const float*)d_in[4];
    const float* swB    = (const float*)d_in[5];
    const int*   tids   = (const int*)d_in[6];
    float* out = (float*)d_out;

    static cudaStream_t s2 = nullptr;
    static cudaEvent_t ev_wAB, ev_weffR;
    if (!s2) {
        cudaStreamCreateWithFlags(&s2, cudaStreamNonBlocking);
        cudaEventCreateWithFlags(&ev_wAB, cudaEventDisableTiming);
        cudaEventCreateWithFlags(&ev_weffR, cudaEventDisableTiming);
        cudaFuncSetAttribute(k_gemm, cudaFuncAttributeMaxDynamicSharedMemorySize, SMEM_TOTAL);
    }

    // main: routing
    k_wAB<<<2048, 256>>>(swA, swB, slog, tids);
    cudaEventRecord(ev_wAB, 0);

    // s2: W_eff for batches 1-15 (fork hangs off ev_wAB)
    cudaStreamWaitEvent(s2, ev_wAB, 0);
    k_weff<<<480, 256, 0, s2>>>(weight, 32);
    cudaEventRecord(ev_weffR, s2);

    // main: batch-0 W_eff slice, then gemm g0 (batch 0; no convert gate!)
    k_weff<<<32, 256>>>(weight, 0);
    k_gemm<<<dim3(OUTF / BN, MG0 / BM), 128, SMEM_TOTAL>>>(bias, out, 0, input);

    // main: gemm g1 (batches 1-15); consumes s2's terminal event -> graph closed
    cudaStreamWaitEvent(0, ev_weffR, 0);
    k_gemm<<<dim3(OUTF / BN, MG1 / BM), 128, SMEM_TOTAL>>>(bias, out, MG0, input);
}